// round 2
// baseline (speedup 1.0000x reference)
#include <cuda_runtime.h>
#include <cstdint>

#define COLS   24576
#define V4     (COLS / 4)      // 6144 float4 per row
#define NBINS  8192            // top-13 bits of monotonic key
#define NT     512             // threads per CTA
#define BPT    (NBINS / NT)    // 16 bins per thread
#define ITER   (V4 / NT)       // 12 float4 per thread
#define NW     (NT / 32)       // 16 warps
#define CAP    1024            // candidate buffer capacity

// Order-preserving float->uint key: larger float => larger key.
__device__ __forceinline__ uint32_t fkey(float f) {
    uint32_t u = __float_as_uint(f);
    return u ^ (uint32_t)(((int32_t)u >> 31) | (int32_t)0x80000000);
}
// Inverse of fkey.
__device__ __forceinline__ float fkey_inv(uint32_t key) {
    uint32_t u = key ^ ((key & 0x80000000u) ? 0x80000000u : 0xFFFFFFFFu);
    return __uint_as_float(u);
}

__global__ __launch_bounds__(NT) void topk_scatter_kernel(
    const float* __restrict__ z,
    const int*   __restrict__ kin,
    float*       __restrict__ out)
{
    __shared__ uint32_t hist[NBINS];       // 32 KB
    __shared__ uint32_t candKey[CAP];      // 4 KB
    __shared__ uint16_t candIdx[CAP];      // 2 KB
    __shared__ uint32_t warpTot[NW];
    __shared__ uint32_t s_binB, s_above, s_cnt;

    const int tid  = threadIdx.x;
    const int lane = tid & 31;
    const int wid  = tid >> 5;
    const int row  = blockIdx.x;
    const uint32_t k = (uint32_t)(kin ? *kin : 64);

    const float4* zr  = reinterpret_cast<const float4*>(z)   + (size_t)row * V4;
    float4*       orw = reinterpret_cast<float4*>(out)       + (size_t)row * V4;
    float*        orow = out + (size_t)row * COLS;

    for (int i = tid; i < NBINS; i += NT) hist[i] = 0;
    if (tid == 0) s_cnt = 0;
    __syncthreads();

    // ---- Pass 1: 13-bit histogram, 4 loads in flight per iteration ----
    #pragma unroll
    for (int ii = 0; ii < ITER; ii += 4) {
        float4 a = zr[tid + (ii + 0) * NT];
        float4 b = zr[tid + (ii + 1) * NT];
        float4 c = zr[tid + (ii + 2) * NT];
        float4 d = zr[tid + (ii + 3) * NT];
        atomicAdd(&hist[fkey(a.x) >> 19], 1u);
        atomicAdd(&hist[fkey(a.y) >> 19], 1u);
        atomicAdd(&hist[fkey(a.z) >> 19], 1u);
        atomicAdd(&hist[fkey(a.w) >> 19], 1u);
        atomicAdd(&hist[fkey(b.x) >> 19], 1u);
        atomicAdd(&hist[fkey(b.y) >> 19], 1u);
        atomicAdd(&hist[fkey(b.z) >> 19], 1u);
        atomicAdd(&hist[fkey(b.w) >> 19], 1u);
        atomicAdd(&hist[fkey(c.x) >> 19], 1u);
        atomicAdd(&hist[fkey(c.y) >> 19], 1u);
        atomicAdd(&hist[fkey(c.z) >> 19], 1u);
        atomicAdd(&hist[fkey(c.w) >> 19], 1u);
        atomicAdd(&hist[fkey(d.x) >> 19], 1u);
        atomicAdd(&hist[fkey(d.y) >> 19], 1u);
        atomicAdd(&hist[fkey(d.z) >> 19], 1u);
        atomicAdd(&hist[fkey(d.w) >> 19], 1u);
    }
    __syncthreads();

    // ---- Warp-shuffle suffix scan to locate the rank-k bin (2 barriers) ----
    const int base = tid * BPT;
    uint32_t s = 0;
    #pragma unroll
    for (int j = 0; j < BPT; j++) s += hist[base + j];
    uint32_t inc = s;                               // inclusive suffix within warp
    #pragma unroll
    for (int off = 1; off < 32; off <<= 1) {
        uint32_t o = __shfl_down_sync(0xFFFFFFFFu, inc, off);
        if (lane + off < 32) inc += o;
    }
    if (lane == 0) warpTot[wid] = inc;              // warp total
    __syncthreads();
    uint32_t ws = 0;
    #pragma unroll
    for (int w = 0; w < NW; w++) if (w > wid) ws += warpTot[w];
    uint32_t abv  = ws + (inc - s);                 // strictly above this thread's bins
    uint32_t incl = ws + inc;
    if (abv < k && incl >= k) {                     // exactly one thread matches
        uint32_t a = abv;
        #pragma unroll
        for (int j = BPT - 1; j >= 0; j--) {
            uint32_t c = hist[base + j];
            if (a + c >= k) { s_binB = (uint32_t)(base + j); s_above = a; break; }
            a += c;
        }
    }
    __syncthreads();
    const uint32_t binB = s_binB;
    const uint32_t need = k - s_above;              // winners inside bin binB

    // ---- Pass 2 (fused): read (L2), write full output, collect candidates ----
    #pragma unroll
    for (int ii = 0; ii < ITER; ii += 4) {
        float4 v0 = zr[tid + (ii + 0) * NT];
        float4 v1 = zr[tid + (ii + 1) * NT];
        float4 v2 = zr[tid + (ii + 2) * NT];
        float4 v3 = zr[tid + (ii + 3) * NT];
        #pragma unroll
        for (int q = 0; q < 4; q++) {
            float4 v = (q == 0) ? v0 : (q == 1) ? v1 : (q == 2) ? v2 : v3;
            uint32_t i4 = (uint32_t)(4 * (tid + (ii + q) * NT));
            uint32_t k0 = fkey(v.x), k1 = fkey(v.y), k2 = fkey(v.z), k3 = fkey(v.w);
            uint32_t b0 = k0 >> 19, b1 = k1 >> 19, b2 = k2 >> 19, b3 = k3 >> 19;
            float4 o;
            o.x = (b0 > binB) ? v.x : 0.0f;
            o.y = (b1 > binB) ? v.y : 0.0f;
            o.z = (b2 > binB) ? v.z : 0.0f;
            o.w = (b3 > binB) ? v.w : 0.0f;
            orw[tid + (ii + q) * NT] = o;
            if (b0 == binB) { uint32_t p = atomicAdd(&s_cnt, 1u); if (p < CAP) { candKey[p] = k0; candIdx[p] = (uint16_t)(i4 + 0); } }
            if (b1 == binB) { uint32_t p = atomicAdd(&s_cnt, 1u); if (p < CAP) { candKey[p] = k1; candIdx[p] = (uint16_t)(i4 + 1); } }
            if (b2 == binB) { uint32_t p = atomicAdd(&s_cnt, 1u); if (p < CAP) { candKey[p] = k2; candIdx[p] = (uint16_t)(i4 + 2); } }
            if (b3 == binB) { uint32_t p = atomicAdd(&s_cnt, 1u); if (p < CAP) { candKey[p] = k3; candIdx[p] = (uint16_t)(i4 + 3); } }
        }
    }
    __syncthreads();
    const uint32_t n = min(s_cnt, (uint32_t)CAP);

    // ---- Exact rank among candidates (key desc, idx asc); winners fix up output ----
    for (uint32_t j = tid; j < n; j += NT) {
        uint32_t kj = candKey[j];
        uint32_t ij = candIdx[j];
        uint32_t r = 0;
        for (uint32_t m = 0; m < n; m++) {
            uint32_t km = candKey[m];
            r += (km > kj) || (km == kj && candIdx[m] < ij);
        }
        if (r < need) orow[ij] = fkey_inv(kj);   // exactly `need` winners
    }
}

extern "C" void kernel_launch(void* const* d_in, const int* in_sizes, int n_in,
                              void* d_out, int out_size) {
    const float* z   = (const float*)d_in[0];
    const int*   kin = (n_in >= 2) ? (const int*)d_in[1] : nullptr;
    float*       out = (float*)d_out;
    int rows = in_sizes[0] / COLS;   // 8192
    topk_scatter_kernel<<<rows, NT>>>(z, kin, out);
}

// round 6
// speedup vs baseline: 2.2111x; 2.2111x over previous
#include <cuda_runtime.h>
#include <cstdint>

#define COLS   24576
#define V4     (COLS / 4)      // 6144 float4 per row
#define NBINS  8192            // top-13 bits of monotonic key
#define NT     512             // threads per CTA
#define BPT    (NBINS / NT)    // 16 bins per thread
#define NW     (NT / 32)       // 16 warps
#define CAP    1024            // candidate buffer capacity

// Order-preserving float->uint key: larger float => larger key.
__device__ __forceinline__ uint32_t fkey(float f) {
    uint32_t u = __float_as_uint(f);
    return u ^ (uint32_t)(((int32_t)u >> 31) | (int32_t)0x80000000);
}
// Inverse of fkey.
__device__ __forceinline__ float fkey_inv(uint32_t key) {
    uint32_t u = key ^ ((key & 0x80000000u) ? 0x80000000u : 0xFFFFFFFFu);
    return __uint_as_float(u);
}

__global__ __launch_bounds__(NT, 4) void topk_scatter_kernel(
    const float* __restrict__ z,
    const int*   __restrict__ kin,
    float*       __restrict__ out)
{
    __shared__ uint32_t hist[NBINS];       // 32 KB
    __shared__ uint32_t candKey[CAP];      // 4 KB
    __shared__ uint16_t candIdx[CAP];      // 2 KB
    __shared__ uint32_t warpTot[NW];
    __shared__ uint32_t s_binB, s_above, s_cnt;

    const int tid  = threadIdx.x;
    const int lane = tid & 31;
    const int wid  = tid >> 5;
    const int row  = blockIdx.x;
    const uint32_t k = (uint32_t)(kin ? *kin : 64);

    const float4* zr  = reinterpret_cast<const float4*>(z) + (size_t)row * V4;
    float4*       orw = reinterpret_cast<float4*>(out)     + (size_t)row * V4;
    float*        orow = out + (size_t)row * COLS;

    for (int i = tid; i < NBINS; i += NT) hist[i] = 0;
    if (tid == 0) s_cnt = 0;
    __syncthreads();

    // ---- Pass 1: 13-bit histogram (HBM read) ----
    #pragma unroll 1
    for (int i = tid; i < V4; i += NT) {
        float4 v = zr[i];
        atomicAdd(&hist[fkey(v.x) >> 19], 1u);
        atomicAdd(&hist[fkey(v.y) >> 19], 1u);
        atomicAdd(&hist[fkey(v.z) >> 19], 1u);
        atomicAdd(&hist[fkey(v.w) >> 19], 1u);
    }
    __syncthreads();

    // ---- Warp-shuffle suffix scan to locate the rank-k bin ----
    const int base = tid * BPT;
    uint32_t s = 0;
    #pragma unroll
    for (int j = 0; j < BPT; j++) s += hist[base + j];
    uint32_t inc = s;                               // inclusive suffix within warp
    #pragma unroll
    for (int off = 1; off < 32; off <<= 1) {
        uint32_t o = __shfl_down_sync(0xFFFFFFFFu, inc, off);
        if (lane + off < 32) inc += o;
    }
    if (lane == 0) warpTot[wid] = inc;              // warp total
    __syncthreads();
    uint32_t ws = 0;
    #pragma unroll
    for (int w = 0; w < NW; w++) if (w > wid) ws += warpTot[w];
    uint32_t abv  = ws + (inc - s);                 // strictly above this thread's bins
    uint32_t incl = ws + inc;
    if (abv < k && incl >= k) {                     // exactly one thread matches
        uint32_t a = abv;
        #pragma unroll
        for (int j = BPT - 1; j >= 0; j--) {
            uint32_t c = hist[base + j];
            if (a + c >= k) { s_binB = (uint32_t)(base + j); s_above = a; break; }
            a += c;
        }
    }
    __syncthreads();
    const uint32_t binB = s_binB;
    const uint32_t need = k - s_above;              // winners inside threshold bin

    // Float thresholds for the hot loop: bin(v) > binB  <=>  v >= hiThr
    //                                    bin(v) == binB <=>  loThr <= v < hiThr
    const float hiThr = fkey_inv((binB + 1u) << 19);
    const float loThr = fkey_inv(binB << 19);

    // ---- Pass 2 (fused): re-read (L2), write output, collect candidates ----
    #pragma unroll 1
    for (int i = tid; i < V4; i += NT) {
        float4 v = zr[i];
        float4 o;
        o.x = (v.x >= hiThr) ? v.x : 0.0f;
        o.y = (v.y >= hiThr) ? v.y : 0.0f;
        o.z = (v.z >= hiThr) ? v.z : 0.0f;
        o.w = (v.w >= hiThr) ? v.w : 0.0f;
        __stcs(&orw[i], o);                         // evict-first: protect z in L2
        // Rare path: candidates in the threshold bin (~25 per row total)
        if (v.x >= loThr && v.x < hiThr) { uint32_t p = atomicAdd(&s_cnt, 1u); if (p < CAP) { candKey[p] = fkey(v.x); candIdx[p] = (uint16_t)(4*i+0); } }
        if (v.y >= loThr && v.y < hiThr) { uint32_t p = atomicAdd(&s_cnt, 1u); if (p < CAP) { candKey[p] = fkey(v.y); candIdx[p] = (uint16_t)(4*i+1); } }
        if (v.z >= loThr && v.z < hiThr) { uint32_t p = atomicAdd(&s_cnt, 1u); if (p < CAP) { candKey[p] = fkey(v.z); candIdx[p] = (uint16_t)(4*i+2); } }
        if (v.w >= loThr && v.w < hiThr) { uint32_t p = atomicAdd(&s_cnt, 1u); if (p < CAP) { candKey[p] = fkey(v.w); candIdx[p] = (uint16_t)(4*i+3); } }
    }
    __syncthreads();
    const uint32_t n = min(s_cnt, (uint32_t)CAP);

    // ---- Exact rank among candidates (key desc, idx asc); winners fix up output ----
    for (uint32_t j = tid; j < n; j += NT) {
        uint32_t kj = candKey[j];
        uint32_t ij = candIdx[j];
        uint32_t r = 0;
        for (uint32_t m = 0; m < n; m++) {
            uint32_t km = candKey[m];
            r += (km > kj) || (km == kj && candIdx[m] < ij);
        }
        if (r < need) orow[ij] = fkey_inv(kj);      // exactly `need` winners
    }
}

extern "C" void kernel_launch(void* const* d_in, const int* in_sizes, int n_in,
                              void* d_out, int out_size) {
    const float* z   = (const float*)d_in[0];
    const int*   kin = (n_in >= 2) ? (const int*)d_in[1] : nullptr;
    float*       out = (float*)d_out;
    int rows = in_sizes[0] / COLS;   // 8192
    topk_scatter_kernel<<<rows, NT>>>(z, kin, out);
}